// round 1
// baseline (speedup 1.0000x reference)
#include <cuda_runtime.h>

// ---------------------------------------------------------------------------
// FastNN: 2x sparse-block conv stages + FC + softmax, fp32.
// Stage kernels: one CTA per 16x16 spatial tile, fully fused
// (channel 1x1 conv + BN, activity test, bottleneck 1x1/3x3/1x1 + BN on active
// tiles only, fused 2x2 maxpool on output).
// ---------------------------------------------------------------------------

#define EPSV 1e-5f

// scratch (no cudaMalloc allowed)
__device__ float g_x1p[16 * 16 * 256 * 256];   // stage1 output, pooled  [N,16,256,256]
__device__ float g_mask2[16 * 256 * 256];      // pooled mask            [N,256,256]
__device__ float g_x2p[16 * 8 * 128 * 128];    // stage2 output, pooled  [N,8,128,128]

// ---------------------------------------------------------------------------
// Stage 1: x[16,3,512,512] -> x1p[16,16,256,256], mask -> mask2
// grid = 16*32*32 CTAs, 256 threads
// ---------------------------------------------------------------------------
__global__ void __launch_bounds__(256, 2) stage1_kernel(
    const float* __restrict__ x, const float* __restrict__ mask,
    const float* __restrict__ cw, const float* __restrict__ cb, const float* __restrict__ bn0,
    const float* __restrict__ d1w, const float* __restrict__ d1b, const float* __restrict__ bn1,
    const float* __restrict__ d2w, const float* __restrict__ d2b, const float* __restrict__ bn2,
    const float* __restrict__ d3w, const float* __restrict__ d3b, const float* __restrict__ bn3)
{
    extern __shared__ float sm[];
    float* s_xc = sm;              // 16*256 (also reused for final 16-ch tile)
    float* s_a  = sm + 16 * 256;   // 32*256 (y1)
    float* s_b  = sm + 48 * 256;   // 32*256 (y2)

    __shared__ float s_red[256];
    __shared__ float s_sc0[16], s_sh0[16];
    __shared__ float s_sc1[32], s_sh1[32];
    __shared__ float s_sc2[32], s_sh2[32];
    __shared__ float s_sc3[16], s_sh3[16];
    __shared__ int s_active;

    const int bid = blockIdx.x;
    const int n   = bid >> 10;
    const int by  = (bid >> 5) & 31;
    const int bx  = bid & 31;
    const int tid = threadIdx.x;
    const int py  = tid >> 4, px = tid & 15;
    const int gy  = by * 16 + py, gx = bx * 16 + px;

    // BN affine precompute: scale = g*rsqrt(v+eps), shift = beta - scale*mean
    if (tid < 16) {
        float g = bn0[tid], b = bn0[16 + tid], m = bn0[32 + tid], v = bn0[48 + tid];
        float s = g * rsqrtf(v + EPSV); s_sc0[tid] = s; s_sh0[tid] = b - s * m;
    } else if (tid < 48) {
        int c = tid - 16;
        float g = bn1[c], b = bn1[32 + c], m = bn1[64 + c], v = bn1[96 + c];
        float s = g * rsqrtf(v + EPSV); s_sc1[c] = s; s_sh1[c] = b - s * m;
    } else if (tid < 80) {
        int c = tid - 48;
        float g = bn2[c], b = bn2[32 + c], m = bn2[64 + c], v = bn2[96 + c];
        float s = g * rsqrtf(v + EPSV); s_sc2[c] = s; s_sh2[c] = b - s * m;
    } else if (tid < 96) {
        int c = tid - 80;
        float g = bn3[c], b = bn3[16 + c], m = bn3[32 + c], v = bn3[48 + c];
        float s = g * rsqrtf(v + EPSV); s_sc3[c] = s; s_sh3[c] = b - s * m;
    }

    // mask tile
    float mval = mask[(n * 512 + gy) * 512 + gx];
    s_red[tid] = mval;
    __syncthreads();

    // pooled mask2 (maxpool 2x2)
    if (tid < 64) {
        int qy = tid >> 3, qx = tid & 7;
        int p0 = (qy * 2) * 16 + qx * 2;
        float m0 = fmaxf(fmaxf(s_red[p0], s_red[p0 + 1]),
                         fmaxf(s_red[p0 + 16], s_red[p0 + 17]));
        g_mask2[(n * 256 + by * 8 + qy) * 256 + (bx * 8 + qx)] = m0;
    }
    __syncthreads();

    // block mean (sum > 128 <=> mean > 0.5)
    for (int s = 128; s > 0; s >>= 1) {
        if (tid < s) s_red[tid] += s_red[tid + s];
        __syncthreads();
    }
    if (tid == 0) s_active = (s_red[0] > 128.0f) ? 1 : 0;

    // channel path: 1x1 conv 3->16 + bias, relu, bn
    const int ibase = ((n * 3) * 512 + gy) * 512 + gx;
    float xv0 = x[ibase];
    float xv1 = x[ibase + 512 * 512];
    float xv2 = x[ibase + 2 * 512 * 512];
#pragma unroll
    for (int c = 0; c < 16; c++) {
        float t = __ldg(&cw[c * 3 + 0]) * xv0 + __ldg(&cw[c * 3 + 1]) * xv1 +
                  __ldg(&cw[c * 3 + 2]) * xv2 + __ldg(&cb[c]);
        t = fmaxf(t, 0.0f);
        s_xc[c * 256 + tid] = fmaf(s_sc0[c], t, s_sh0[c]);
    }
    __syncthreads();   // publishes s_xc and s_active

    // thread tiling for bottleneck convs: 4 pixels x K output channels
    const int c2b8 = (tid & 3) * 8;      // 8 outs (32-ch layers)
    const int pg   = tid >> 2;           // 64 pixel groups
    const int prow = pg >> 2;            // 0..15
    const int pcol = (pg & 3) * 4;       // 0,4,8,12
    const int pix0 = prow * 16 + pcol;

    if (s_active) {
        // ---- d1: 1x1, 16 -> 32 ----
        {
            float acc[8][4];
#pragma unroll
            for (int c2 = 0; c2 < 8; c2++) {
                float bsv = __ldg(&d1b[c2b8 + c2]);
                acc[c2][0] = bsv; acc[c2][1] = bsv; acc[c2][2] = bsv; acc[c2][3] = bsv;
            }
#pragma unroll
            for (int c1 = 0; c1 < 16; c1++) {
                float4 v = *reinterpret_cast<const float4*>(&s_xc[c1 * 256 + pix0]);
#pragma unroll
                for (int c2 = 0; c2 < 8; c2++) {
                    float w = __ldg(&d1w[(c2b8 + c2) * 16 + c1]);
                    acc[c2][0] = fmaf(v.x, w, acc[c2][0]);
                    acc[c2][1] = fmaf(v.y, w, acc[c2][1]);
                    acc[c2][2] = fmaf(v.z, w, acc[c2][2]);
                    acc[c2][3] = fmaf(v.w, w, acc[c2][3]);
                }
            }
#pragma unroll
            for (int c2 = 0; c2 < 8; c2++) {
                int c = c2b8 + c2;
                float sc = s_sc1[c], sh = s_sh1[c];
                float4 o;
                o.x = fmaf(sc, fmaxf(acc[c2][0], 0.0f), sh);
                o.y = fmaf(sc, fmaxf(acc[c2][1], 0.0f), sh);
                o.z = fmaf(sc, fmaxf(acc[c2][2], 0.0f), sh);
                o.w = fmaf(sc, fmaxf(acc[c2][3], 0.0f), sh);
                *reinterpret_cast<float4*>(&s_a[c * 256 + pix0]) = o;
            }
        }
        __syncthreads();

        // ---- d2: 3x3 (block-padded), 32 -> 32 ----
        {
            float acc[8][4];
#pragma unroll
            for (int c2 = 0; c2 < 8; c2++) {
                float bsv = __ldg(&d2b[c2b8 + c2]);
                acc[c2][0] = bsv; acc[c2][1] = bsv; acc[c2][2] = bsv; acc[c2][3] = bsv;
            }
            for (int c1 = 0; c1 < 32; c1++) {
                float v[3][6];
#pragma unroll
                for (int r = 0; r < 3; r++) {
                    int yy = prow - 1 + r;
                    bool yok = (yy >= 0) && (yy < 16);
#pragma unroll
                    for (int j = 0; j < 6; j++) {
                        int xx = pcol - 1 + j;
                        bool ok = yok && (xx >= 0) && (xx < 16);
                        v[r][j] = ok ? s_a[c1 * 256 + yy * 16 + xx] : 0.0f;
                    }
                }
#pragma unroll
                for (int c2 = 0; c2 < 8; c2++) {
                    const float* wp = d2w + ((c2b8 + c2) * 32 + c1) * 9;
#pragma unroll
                    for (int dy = 0; dy < 3; dy++) {
#pragma unroll
                        for (int dx = 0; dx < 3; dx++) {
                            float w = __ldg(&wp[dy * 3 + dx]);
                            acc[c2][0] = fmaf(v[dy][0 + dx], w, acc[c2][0]);
                            acc[c2][1] = fmaf(v[dy][1 + dx], w, acc[c2][1]);
                            acc[c2][2] = fmaf(v[dy][2 + dx], w, acc[c2][2]);
                            acc[c2][3] = fmaf(v[dy][3 + dx], w, acc[c2][3]);
                        }
                    }
                }
            }
#pragma unroll
            for (int c2 = 0; c2 < 8; c2++) {
                int c = c2b8 + c2;
                float sc = s_sc2[c], sh = s_sh2[c];
                float4 o;
                o.x = fmaf(sc, fmaxf(acc[c2][0], 0.0f), sh);
                o.y = fmaf(sc, fmaxf(acc[c2][1], 0.0f), sh);
                o.z = fmaf(sc, fmaxf(acc[c2][2], 0.0f), sh);
                o.w = fmaf(sc, fmaxf(acc[c2][3], 0.0f), sh);
                *reinterpret_cast<float4*>(&s_b[c * 256 + pix0]) = o;
            }
        }
        __syncthreads();

        // ---- d3: 1x1, 32 -> 16 ----
        {
            const int c2b4 = (tid & 3) * 4;
            float acc[4][4];
#pragma unroll
            for (int c2 = 0; c2 < 4; c2++) {
                float bsv = __ldg(&d3b[c2b4 + c2]);
                acc[c2][0] = bsv; acc[c2][1] = bsv; acc[c2][2] = bsv; acc[c2][3] = bsv;
            }
#pragma unroll
            for (int c1 = 0; c1 < 32; c1++) {
                float4 v = *reinterpret_cast<const float4*>(&s_b[c1 * 256 + pix0]);
#pragma unroll
                for (int c2 = 0; c2 < 4; c2++) {
                    float w = __ldg(&d3w[(c2b4 + c2) * 32 + c1]);
                    acc[c2][0] = fmaf(v.x, w, acc[c2][0]);
                    acc[c2][1] = fmaf(v.y, w, acc[c2][1]);
                    acc[c2][2] = fmaf(v.z, w, acc[c2][2]);
                    acc[c2][3] = fmaf(v.w, w, acc[c2][3]);
                }
            }
#pragma unroll
            for (int c2 = 0; c2 < 4; c2++) {
                int c = c2b4 + c2;
                float sc = s_sc3[c], sh = s_sh3[c];
                float4 o;
                o.x = fmaf(sc, fmaxf(acc[c2][0], 0.0f), sh);
                o.y = fmaf(sc, fmaxf(acc[c2][1], 0.0f), sh);
                o.z = fmaf(sc, fmaxf(acc[c2][2], 0.0f), sh);
                o.w = fmaf(sc, fmaxf(acc[c2][3], 0.0f), sh);
                *reinterpret_cast<float4*>(&s_xc[c * 256 + pix0]) = o;
            }
        }
        __syncthreads();
    }

    // fused 2x2 maxpool of final tile (in s_xc), write pooled output
#pragma unroll
    for (int k = 0; k < 4; k++) {
        int o = tid + k * 256;        // 16ch * 64 pooled px = 1024 outputs
        int c = o >> 6;
        int q = o & 63;
        int qy = q >> 3, qx = q & 7;
        const float* sp = &s_xc[c * 256 + (qy * 2) * 16 + qx * 2];
        float mo = fmaxf(fmaxf(sp[0], sp[1]), fmaxf(sp[16], sp[17]));
        g_x1p[((n * 16 + c) * 256 + by * 8 + qy) * 256 + (bx * 8 + qx)] = mo;
    }
}

// ---------------------------------------------------------------------------
// Stage 2: g_x1p[16,16,256,256] -> g_x2p[16,8,128,128]
// grid = 16*16*16 CTAs, 256 threads
// ---------------------------------------------------------------------------
__global__ void __launch_bounds__(256, 2) stage2_kernel(
    const float* __restrict__ cw, const float* __restrict__ cb, const float* __restrict__ bn0,
    const float* __restrict__ d1w, const float* __restrict__ d1b, const float* __restrict__ bn1,
    const float* __restrict__ d2w, const float* __restrict__ d2b, const float* __restrict__ bn2,
    const float* __restrict__ d3w, const float* __restrict__ d3b, const float* __restrict__ bn3)
{
    __shared__ float s_xc[8 * 256];    // channel-path / final tile
    __shared__ float s_a[16 * 256];
    __shared__ float s_b[16 * 256];
    __shared__ float s_red[256];
    __shared__ float s_sc0[8], s_sh0[8];
    __shared__ float s_sc1[16], s_sh1[16];
    __shared__ float s_sc2[16], s_sh2[16];
    __shared__ float s_sc3[8], s_sh3[8];
    __shared__ int s_active;

    const int bid = blockIdx.x;
    const int n   = bid >> 8;
    const int by  = (bid >> 4) & 15;
    const int bx  = bid & 15;
    const int tid = threadIdx.x;
    const int py  = tid >> 4, px = tid & 15;
    const int gy  = by * 16 + py, gx = bx * 16 + px;

    if (tid < 8) {
        float g = bn0[tid], b = bn0[8 + tid], m = bn0[16 + tid], v = bn0[24 + tid];
        float s = g * rsqrtf(v + EPSV); s_sc0[tid] = s; s_sh0[tid] = b - s * m;
    } else if (tid < 24) {
        int c = tid - 8;
        float g = bn1[c], b = bn1[16 + c], m = bn1[32 + c], v = bn1[48 + c];
        float s = g * rsqrtf(v + EPSV); s_sc1[c] = s; s_sh1[c] = b - s * m;
    } else if (tid < 40) {
        int c = tid - 24;
        float g = bn2[c], b = bn2[16 + c], m = bn2[32 + c], v = bn2[48 + c];
        float s = g * rsqrtf(v + EPSV); s_sc2[c] = s; s_sh2[c] = b - s * m;
    } else if (tid < 48) {
        int c = tid - 40;
        float g = bn3[c], b = bn3[8 + c], m = bn3[16 + c], v = bn3[24 + c];
        float s = g * rsqrtf(v + EPSV); s_sc3[c] = s; s_sh3[c] = b - s * m;
    }

    // activity from pooled mask
    s_red[tid] = g_mask2[(n * 256 + gy) * 256 + gx];
    __syncthreads();
    for (int s = 128; s > 0; s >>= 1) {
        if (tid < s) s_red[tid] += s_red[tid + s];
        __syncthreads();
    }
    if (tid == 0) s_active = (s_red[0] > 128.0f) ? 1 : 0;

    // channel path: 1x1 conv 16->8 + bias, relu, bn
    {
        const int ibase = ((n * 16) * 256 + gy) * 256 + gx;
        float xin[16];
#pragma unroll
        for (int c = 0; c < 16; c++) xin[c] = g_x1p[ibase + c * 65536];
#pragma unroll
        for (int c2 = 0; c2 < 8; c2++) {
            float t = __ldg(&cb[c2]);
#pragma unroll
            for (int c1 = 0; c1 < 16; c1++)
                t = fmaf(xin[c1], __ldg(&cw[c2 * 16 + c1]), t);
            t = fmaxf(t, 0.0f);
            s_xc[c2 * 256 + tid] = fmaf(s_sc0[c2], t, s_sh0[c2]);
        }
    }
    __syncthreads();

    const int pg   = tid >> 2;
    const int prow = pg >> 2;
    const int pcol = (pg & 3) * 4;
    const int pix0 = prow * 16 + pcol;

    if (s_active) {
        // ---- d1: 1x1, 8 -> 16 ----
        {
            const int c2b4 = (tid & 3) * 4;
            float acc[4][4];
#pragma unroll
            for (int c2 = 0; c2 < 4; c2++) {
                float bsv = __ldg(&d1b[c2b4 + c2]);
                acc[c2][0] = bsv; acc[c2][1] = bsv; acc[c2][2] = bsv; acc[c2][3] = bsv;
            }
#pragma unroll
            for (int c1 = 0; c1 < 8; c1++) {
                float4 v = *reinterpret_cast<const float4*>(&s_xc[c1 * 256 + pix0]);
#pragma unroll
                for (int c2 = 0; c2 < 4; c2++) {
                    float w = __ldg(&d1w[(c2b4 + c2) * 8 + c1]);
                    acc[c2][0] = fmaf(v.x, w, acc[c2][0]);
                    acc[c2][1] = fmaf(v.y, w, acc[c2][1]);
                    acc[c2][2] = fmaf(v.z, w, acc[c2][2]);
                    acc[c2][3] = fmaf(v.w, w, acc[c2][3]);
                }
            }
#pragma unroll
            for (int c2 = 0; c2 < 4; c2++) {
                int c = c2b4 + c2;
                float sc = s_sc1[c], sh = s_sh1[c];
                float4 o;
                o.x = fmaf(sc, fmaxf(acc[c2][0], 0.0f), sh);
                o.y = fmaf(sc, fmaxf(acc[c2][1], 0.0f), sh);
                o.z = fmaf(sc, fmaxf(acc[c2][2], 0.0f), sh);
                o.w = fmaf(sc, fmaxf(acc[c2][3], 0.0f), sh);
                *reinterpret_cast<float4*>(&s_a[c * 256 + pix0]) = o;
            }
        }
        __syncthreads();

        // ---- d2: 3x3 (block-padded), 16 -> 16 ----
        {
            const int c2b4 = (tid & 3) * 4;
            float acc[4][4];
#pragma unroll
            for (int c2 = 0; c2 < 4; c2++) {
                float bsv = __ldg(&d2b[c2b4 + c2]);
                acc[c2][0] = bsv; acc[c2][1] = bsv; acc[c2][2] = bsv; acc[c2][3] = bsv;
            }
            for (int c1 = 0; c1 < 16; c1++) {
                float v[3][6];
#pragma unroll
                for (int r = 0; r < 3; r++) {
                    int yy = prow - 1 + r;
                    bool yok = (yy >= 0) && (yy < 16);
#pragma unroll
                    for (int j = 0; j < 6; j++) {
                        int xx = pcol - 1 + j;
                        bool ok = yok && (xx >= 0) && (xx < 16);
                        v[r][j] = ok ? s_a[c1 * 256 + yy * 16 + xx] : 0.0f;
                    }
                }
#pragma unroll
                for (int c2 = 0; c2 < 4; c2++) {
                    const float* wp = d2w + ((c2b4 + c2) * 16 + c1) * 9;
#pragma unroll
                    for (int dy = 0; dy < 3; dy++) {
#pragma unroll
                        for (int dx = 0; dx < 3; dx++) {
                            float w = __ldg(&wp[dy * 3 + dx]);
                            acc[c2][0] = fmaf(v[dy][0 + dx], w, acc[c2][0]);
                            acc[c2][1] = fmaf(v[dy][1 + dx], w, acc[c2][1]);
                            acc[c2][2] = fmaf(v[dy][2 + dx], w, acc[c2][2]);
                            acc[c2][3] = fmaf(v[dy][3 + dx], w, acc[c2][3]);
                        }
                    }
                }
            }
#pragma unroll
            for (int c2 = 0; c2 < 4; c2++) {
                int c = c2b4 + c2;
                float sc = s_sc2[c], sh = s_sh2[c];
                float4 o;
                o.x = fmaf(sc, fmaxf(acc[c2][0], 0.0f), sh);
                o.y = fmaf(sc, fmaxf(acc[c2][1], 0.0f), sh);
                o.z = fmaf(sc, fmaxf(acc[c2][2], 0.0f), sh);
                o.w = fmaf(sc, fmaxf(acc[c2][3], 0.0f), sh);
                *reinterpret_cast<float4*>(&s_b[c * 256 + pix0]) = o;
            }
        }
        __syncthreads();

        // ---- d3: 1x1, 16 -> 8 ----
        {
            const int c2b2 = (tid & 3) * 2;
            float acc[2][4];
#pragma unroll
            for (int c2 = 0; c2 < 2; c2++) {
                float bsv = __ldg(&d3b[c2b2 + c2]);
                acc[c2][0] = bsv; acc[c2][1] = bsv; acc[c2][2] = bsv; acc[c2][3] = bsv;
            }
#pragma unroll
            for (int c1 = 0; c1 < 16; c1++) {
                float4 v = *reinterpret_cast<const float4*>(&s_b[c1 * 256 + pix0]);
#pragma unroll
                for (int c2 = 0; c2 < 2; c2++) {
                    float w = __ldg(&d3w[(c2b2 + c2) * 16 + c1]);
                    acc[c2][0] = fmaf(v.x, w, acc[c2][0]);
                    acc[c2][1] = fmaf(v.y, w, acc[c2][1]);
                    acc[c2][2] = fmaf(v.z, w, acc[c2][2]);
                    acc[c2][3] = fmaf(v.w, w, acc[c2][3]);
                }
            }
#pragma unroll
            for (int c2 = 0; c2 < 2; c2++) {
                int c = c2b2 + c2;
                float sc = s_sc3[c], sh = s_sh3[c];
                float4 o;
                o.x = fmaf(sc, fmaxf(acc[c2][0], 0.0f), sh);
                o.y = fmaf(sc, fmaxf(acc[c2][1], 0.0f), sh);
                o.z = fmaf(sc, fmaxf(acc[c2][2], 0.0f), sh);
                o.w = fmaf(sc, fmaxf(acc[c2][3], 0.0f), sh);
                *reinterpret_cast<float4*>(&s_xc[c * 256 + pix0]) = o;
            }
        }
        __syncthreads();
    }

    // fused 2x2 maxpool -> g_x2p  (8ch * 64 px = 512 outputs)
#pragma unroll
    for (int k = 0; k < 2; k++) {
        int o = tid + k * 256;
        int c = o >> 6;
        int q = o & 63;
        int qy = q >> 3, qx = q & 7;
        const float* sp = &s_xc[c * 256 + (qy * 2) * 16 + qx * 2];
        float mo = fmaxf(fmaxf(sp[0], sp[1]), fmaxf(sp[16], sp[17]));
        g_x2p[((n * 8 + c) * 128 + by * 8 + qy) * 128 + (bx * 8 + qx)] = mo;
    }
}

// ---------------------------------------------------------------------------
// FC + softmax: g_x2p[16, 131072] @ fc_w[10,131072]^T + fc_b -> softmax
// ---------------------------------------------------------------------------
__global__ void fc_kernel(const float* __restrict__ fc_w, const float* __restrict__ fc_b,
                          float* __restrict__ out)
{
    const int n = blockIdx.x;
    const int tid = threadIdx.x;
    const float* f = g_x2p + n * 131072;

    float part[10];
#pragma unroll
    for (int k = 0; k < 10; k++) part[k] = 0.0f;

    for (int j = tid; j < 131072; j += 256) {
        float fv = f[j];
#pragma unroll
        for (int k = 0; k < 10; k++)
            part[k] = fmaf(fv, __ldg(&fc_w[k * 131072 + j]), part[k]);
    }

    __shared__ float sred[10][256];
#pragma unroll
    for (int k = 0; k < 10; k++) sred[k][tid] = part[k];
    __syncthreads();
    for (int s = 128; s > 0; s >>= 1) {
        if (tid < s) {
#pragma unroll
            for (int k = 0; k < 10; k++) sred[k][tid] += sred[k][tid + s];
        }
        __syncthreads();
    }

    if (tid == 0) {
        float l[10];
        float mx = -1e30f;
#pragma unroll
        for (int k = 0; k < 10; k++) {
            l[k] = sred[k][0] + fc_b[k];
            mx = fmaxf(mx, l[k]);
        }
        float se = 0.0f;
#pragma unroll
        for (int k = 0; k < 10; k++) { l[k] = expf(l[k] - mx); se += l[k]; }
        float inv = 1.0f / se;
#pragma unroll
        for (int k = 0; k < 10; k++) out[n * 10 + k] = l[k] * inv;
    }
}

// ---------------------------------------------------------------------------
extern "C" void kernel_launch(void* const* d_in, const int* in_sizes, int n_in,
                              void* d_out, int out_size)
{
    const float* x      = (const float*)d_in[0];
    const float* mask   = (const float*)d_in[1];
    const float* s1_cw  = (const float*)d_in[2];
    const float* s1_cb  = (const float*)d_in[3];
    const float* s1_bn0 = (const float*)d_in[4];
    const float* s1_d1w = (const float*)d_in[5];
    const float* s1_d1b = (const float*)d_in[6];
    const float* s1_bn1 = (const float*)d_in[7];
    const float* s1_d2w = (const float*)d_in[8];
    const float* s1_d2b = (const float*)d_in[9];
    const float* s1_bn2 = (const float*)d_in[10];
    const float* s1_d3w = (const float*)d_in[11];
    const float* s1_d3b = (const float*)d_in[12];
    const float* s1_bn3 = (const float*)d_in[13];
    const float* s2_cw  = (const float*)d_in[14];
    const float* s2_cb  = (const float*)d_in[15];
    const float* s2_bn0 = (const float*)d_in[16];
    const float* s2_d1w = (const float*)d_in[17];
    const float* s2_d1b = (const float*)d_in[18];
    const float* s2_bn1 = (const float*)d_in[19];
    const float* s2_d2w = (const float*)d_in[20];
    const float* s2_d2b = (const float*)d_in[21];
    const float* s2_bn2 = (const float*)d_in[22];
    const float* s2_d3w = (const float*)d_in[23];
    const float* s2_d3b = (const float*)d_in[24];
    const float* s2_bn3 = (const float*)d_in[25];
    const float* fc_w   = (const float*)d_in[26];
    const float* fc_b   = (const float*)d_in[27];

    const int smem1 = 80 * 256 * sizeof(float);   // 80 KB dynamic
    cudaFuncSetAttribute(stage1_kernel, cudaFuncAttributeMaxDynamicSharedMemorySize, smem1);

    stage1_kernel<<<16 * 32 * 32, 256, smem1>>>(
        x, mask, s1_cw, s1_cb, s1_bn0, s1_d1w, s1_d1b, s1_bn1,
        s1_d2w, s1_d2b, s1_bn2, s1_d3w, s1_d3b, s1_bn3);

    stage2_kernel<<<16 * 16 * 16, 256>>>(
        s2_cw, s2_cb, s2_bn0, s2_d1w, s2_d1b, s2_bn1,
        s2_d2w, s2_d2b, s2_bn2, s2_d3w, s2_d3b, s2_bn3);

    fc_kernel<<<16, 256>>>(fc_w, fc_b, (float*)d_out);
}

// round 2
// speedup vs baseline: 2.4467x; 2.4467x over previous
#include <cuda_runtime.h>

#define EPSV 1e-5f

// scratch (no cudaMalloc allowed)
__device__ float g_x1p[16 * 16 * 256 * 256];   // stage1 output, pooled  [N,16,256,256]
__device__ float g_mask2[16 * 256 * 256];      // pooled mask            [N,256,256]
__device__ float g_x2p[16 * 8 * 128 * 128];    // stage2 output, pooled  [N,8,128,128]
__device__ float g_fcpart[16 * 8 * 10];        // FC partial sums

typedef unsigned long long ull;

__device__ __forceinline__ void fma2(ull& d, ull a, ull b) {
    asm("fma.rn.f32x2 %0, %1, %2, %0;" : "+l"(d) : "l"(a), "l"(b));
}
__device__ __forceinline__ ull pack2(float lo, float hi) {
    ull r; asm("mov.b64 %0, {%1, %2};" : "=l"(r) : "f"(lo), "f"(hi)); return r;
}
__device__ __forceinline__ ull dup2(float v) { return pack2(v, v); }
__device__ __forceinline__ float2 unpack2(ull u) {
    float2 f; asm("mov.b64 {%0, %1}, %2;" : "=f"(f.x), "=f"(f.y) : "l"(u)); return f;
}

// ---------------------------------------------------------------------------
// Stage 1: x[16,3,512,512] -> g_x1p[16,16,256,256], mask -> g_mask2
// one CTA per 16x16 tile; 256 threads.
// thread map for bottleneck convs: c2 group = tid>>6 (warp-uniform),
// pixel group = tid&63 -> 4 horizontally-adjacent pixels.
// ---------------------------------------------------------------------------
__global__ void __launch_bounds__(256, 2) stage1_kernel(
    const float* __restrict__ x, const float* __restrict__ mask,
    const float* __restrict__ cw, const float* __restrict__ cb, const float* __restrict__ bn0,
    const float* __restrict__ d1w, const float* __restrict__ d1b, const float* __restrict__ bn1,
    const float* __restrict__ d2w, const float* __restrict__ d2b, const float* __restrict__ bn2,
    const float* __restrict__ d3w, const float* __restrict__ d3b, const float* __restrict__ bn3)
{
    extern __shared__ float sm[];
    float*  s_a   = sm;                         // 32*256 floats (d1 out, then d3 out)
    float*  s_b   = sm + 8192;                  // 32*256 floats (d2 out); s_xc aliases
    float*  s_xc  = s_b;                        // 16*256 floats (channel-path out)
    float2* w2d2  = (float2*)(sm + 16384);      // [c1=32][tap=9][pair=16]
    float*  w2d2f = (float*)w2d2;
    float2* w2d1  = (float2*)(sm + 16384 + 9216);   // [c1=16][pair=16]
    float*  w2d1f = (float*)w2d1;
    float2* w2d3  = w2d1 + 256;                 // [c1=32][pair=8]
    float*  w2d3f = (float*)w2d3;

    __shared__ float s_red[256];
    __shared__ float s_wsum[8];
    __shared__ float s_sc0[16], s_sh0[16];
    __shared__ float s_sc1[32], s_sh1[32];
    __shared__ float s_sc2[32], s_sh2[32];
    __shared__ float s_sc3[16], s_sh3[16];
    __shared__ int s_active;

    const int bid = blockIdx.x;
    const int n   = bid >> 10;
    const int by  = (bid >> 5) & 31;
    const int bx  = bid & 31;
    const int tid = threadIdx.x;
    const int py  = tid >> 4, px_ = tid & 15;
    const int gy  = by * 16 + py, gx = bx * 16 + px_;

    // BN affine precompute
    if (tid < 16) {
        float g = bn0[tid], b = bn0[16 + tid], m = bn0[32 + tid], v = bn0[48 + tid];
        float s = g * rsqrtf(v + EPSV); s_sc0[tid] = s; s_sh0[tid] = b - s * m;
    } else if (tid < 48) {
        int c = tid - 16;
        float g = bn1[c], b = bn1[32 + c], m = bn1[64 + c], v = bn1[96 + c];
        float s = g * rsqrtf(v + EPSV); s_sc1[c] = s; s_sh1[c] = b - s * m;
    } else if (tid < 80) {
        int c = tid - 48;
        float g = bn2[c], b = bn2[32 + c], m = bn2[64 + c], v = bn2[96 + c];
        float s = g * rsqrtf(v + EPSV); s_sc2[c] = s; s_sh2[c] = b - s * m;
    } else if (tid < 96) {
        int c = tid - 80;
        float g = bn3[c], b = bn3[16 + c], m = bn3[32 + c], v = bn3[48 + c];
        float s = g * rsqrtf(v + EPSV); s_sc3[c] = s; s_sh3[c] = b - s * m;
    }

    // mask: tile into s_red for pooled-mask output + warp-shuffle sum for activity
    float mval = mask[(n * 512 + gy) * 512 + gx];
    s_red[tid] = mval;
    float msum = mval;
#pragma unroll
    for (int o = 16; o; o >>= 1) msum += __shfl_xor_sync(0xffffffffu, msum, o);
    if ((tid & 31) == 0) s_wsum[tid >> 5] = msum;
    __syncthreads();

    if (tid < 64) {
        int qy = tid >> 3, qx = tid & 7;
        int p0 = (qy * 2) * 16 + qx * 2;
        float m0 = fmaxf(fmaxf(s_red[p0], s_red[p0 + 1]),
                         fmaxf(s_red[p0 + 16], s_red[p0 + 17]));
        g_mask2[(n * 256 + by * 8 + qy) * 256 + (bx * 8 + qx)] = m0;
    }
    if (tid == 0) {
        float t = 0.f;
#pragma unroll
        for (int i = 0; i < 8; i++) t += s_wsum[i];
        s_active = (t > 128.0f) ? 1 : 0;
    }

    // channel path: 1x1 conv 3->16 + bias, relu, bn  (writes s_xc)
    {
        const int ibase = ((n * 3) * 512 + gy) * 512 + gx;
        float xv0 = x[ibase];
        float xv1 = x[ibase + 512 * 512];
        float xv2 = x[ibase + 2 * 512 * 512];
#pragma unroll
        for (int c = 0; c < 16; c++) {
            float t = __ldg(&cw[c * 3 + 0]) * xv0 + __ldg(&cw[c * 3 + 1]) * xv1 +
                      __ldg(&cw[c * 3 + 2]) * xv2 + __ldg(&cb[c]);
            t = fmaxf(t, 0.0f);
            s_xc[c * 256 + tid] = fmaf(s_sc0[c], t, s_sh0[c]);
        }
    }
    __syncthreads();   // publishes s_xc, s_active, BN params

    const int c2g  = tid >> 6;        // warp-uniform output-channel group
    const int pg   = tid & 63;        // pixel group: 4 adjacent pixels
    const int prow = pg >> 2;         // 0..15
    const int pcol = (pg & 3) * 4;    // 0,4,8,12
    const int pix0 = prow * 16 + pcol;

    if (s_active) {
        // ---- weight prep: coalesced LDG, paired c2 layout in SMEM ----
        // d2w [32c2][32c1][9] -> w2d2[(c1*9+t)*16 + c2/2].{x,y}
        for (int i = tid; i < 9216; i += 256) {
            int c2 = i / 288, rem = i - c2 * 288;
            int c1 = rem / 9, t = rem - c1 * 9;
            w2d2f[((c1 * 9 + t) * 16 + (c2 >> 1)) * 2 + (c2 & 1)] = d2w[i];
        }
        // d1w [32c2][16c1] -> w2d1[c1*16 + c2/2]
        for (int i = tid; i < 512; i += 256) {
            int c2 = i >> 4, c1 = i & 15;
            w2d1f[(c1 * 16 + (c2 >> 1)) * 2 + (c2 & 1)] = d1w[i];
        }
        // d3w [16c2][32c1] -> w2d3[c1*8 + c2/2]
        for (int i = tid; i < 512; i += 256) {
            int c2 = i >> 5, c1 = i & 31;
            w2d3f[(c1 * 8 + (c2 >> 1)) * 2 + (c2 & 1)] = d3w[i];
        }
        __syncthreads();

        // ---- d1: 1x1, 16 -> 32 ----
        {
            const int pbase = c2g * 4;   // of 16 pairs
            ull acc[4][4];
#pragma unroll
            for (int p = 0; p < 4; p++) {
                int c2 = 2 * (pbase + p);
                ull bv = pack2(__ldg(&d1b[c2]), __ldg(&d1b[c2 + 1]));
                acc[p][0] = bv; acc[p][1] = bv; acc[p][2] = bv; acc[p][3] = bv;
            }
#pragma unroll
            for (int c1 = 0; c1 < 16; c1++) {
                float4 v = *(const float4*)&s_xc[c1 * 256 + pix0];
                ull vd[4] = {dup2(v.x), dup2(v.y), dup2(v.z), dup2(v.w)};
                const float2* wp = w2d1 + c1 * 16 + pbase;
                ulonglong2 wA = *(const ulonglong2*)wp;
                ulonglong2 wB = *(const ulonglong2*)(wp + 2);
#pragma unroll
                for (int p4 = 0; p4 < 4; p4++) {
                    fma2(acc[0][p4], wA.x, vd[p4]);
                    fma2(acc[1][p4], wA.y, vd[p4]);
                    fma2(acc[2][p4], wB.x, vd[p4]);
                    fma2(acc[3][p4], wB.y, vd[p4]);
                }
            }
#pragma unroll
            for (int p = 0; p < 4; p++) {
                int c2 = 2 * (pbase + p);
                float sa = s_sc1[c2], ha = s_sh1[c2];
                float sb2 = s_sc1[c2 + 1], hb = s_sh1[c2 + 1];
#pragma unroll
                for (int p4 = 0; p4 < 4; p4++) {
                    float2 f = unpack2(acc[p][p4]);
                    s_a[c2 * 256 + pix0 + p4]       = fmaf(sa, fmaxf(f.x, 0.f), ha);
                    s_a[(c2 + 1) * 256 + pix0 + p4] = fmaf(sb2, fmaxf(f.y, 0.f), hb);
                }
            }
        }
        __syncthreads();

        // ---- d2: 3x3 (block-padded), 32 -> 32 ----
        {
            const int pbase = c2g * 4;   // of 16 pairs
            ull acc[4][4];
#pragma unroll
            for (int p = 0; p < 4; p++) {
                int c2 = 2 * (pbase + p);
                ull bv = pack2(__ldg(&d2b[c2]), __ldg(&d2b[c2 + 1]));
                acc[p][0] = bv; acc[p][1] = bv; acc[p][2] = bv; acc[p][3] = bv;
            }
            const float* basep = s_a + pcol;
#pragma unroll 2
            for (int c1 = 0; c1 < 32; c1++) {
                const float* cbase = basep + c1 * 256;
#pragma unroll
                for (int r = 0; r < 3; r++) {
                    int yy = prow - 1 + r;
                    float v0, v1, v2, v3, v4, v5;
                    if ((unsigned)yy < 16u) {
                        const float* rp = cbase + yy * 16;
                        float4 m = *(const float4*)rp;
                        v1 = m.x; v2 = m.y; v3 = m.z; v4 = m.w;
                        v0 = (pcol > 0)  ? rp[-1] : 0.f;
                        v5 = (pcol < 12) ? rp[4]  : 0.f;
                    } else { v0 = v1 = v2 = v3 = v4 = v5 = 0.f; }
                    ull vd[6] = {dup2(v0), dup2(v1), dup2(v2), dup2(v3), dup2(v4), dup2(v5)};
                    const float2* wrow = w2d2 + (c1 * 9 + r * 3) * 16 + pbase;
#pragma unroll
                    for (int dx = 0; dx < 3; dx++) {
                        const float2* wp = wrow + dx * 16;
                        ulonglong2 wA = *(const ulonglong2*)wp;
                        ulonglong2 wB = *(const ulonglong2*)(wp + 2);
#pragma unroll
                        for (int p4 = 0; p4 < 4; p4++) {
                            fma2(acc[0][p4], wA.x, vd[dx + p4]);
                            fma2(acc[1][p4], wA.y, vd[dx + p4]);
                            fma2(acc[2][p4], wB.x, vd[dx + p4]);
                            fma2(acc[3][p4], wB.y, vd[dx + p4]);
                        }
                    }
                }
            }
            __syncthreads();   // done reading s_a (d1 data) before d3 overwrites
#pragma unroll
            for (int p = 0; p < 4; p++) {
                int c2 = 2 * (pbase + p);
                float sa = s_sc2[c2], ha = s_sh2[c2];
                float sb2 = s_sc2[c2 + 1], hb = s_sh2[c2 + 1];
#pragma unroll
                for (int p4 = 0; p4 < 4; p4++) {
                    float2 f = unpack2(acc[p][p4]);
                    s_b[c2 * 256 + pix0 + p4]       = fmaf(sa, fmaxf(f.x, 0.f), ha);
                    s_b[(c2 + 1) * 256 + pix0 + p4] = fmaf(sb2, fmaxf(f.y, 0.f), hb);
                }
            }
        }
        __syncthreads();

        // ---- d3: 1x1, 32 -> 16 ----  (writes s_a)
        {
            const int pbase = c2g * 2;   // of 8 pairs
            ull acc[2][4];
#pragma unroll
            for (int p = 0; p < 2; p++) {
                int c2 = 2 * (pbase + p);
                ull bv = pack2(__ldg(&d3b[c2]), __ldg(&d3b[c2 + 1]));
                acc[p][0] = bv; acc[p][1] = bv; acc[p][2] = bv; acc[p][3] = bv;
            }
#pragma unroll
            for (int c1 = 0; c1 < 32; c1++) {
                float4 v = *(const float4*)&s_b[c1 * 256 + pix0];
                ull vd[4] = {dup2(v.x), dup2(v.y), dup2(v.z), dup2(v.w)};
                ulonglong2 w = *(const ulonglong2*)(w2d3 + c1 * 8 + pbase);
#pragma unroll
                for (int p4 = 0; p4 < 4; p4++) {
                    fma2(acc[0][p4], w.x, vd[p4]);
                    fma2(acc[1][p4], w.y, vd[p4]);
                }
            }
#pragma unroll
            for (int p = 0; p < 2; p++) {
                int c2 = 2 * (pbase + p);
                float sa = s_sc3[c2], ha = s_sh3[c2];
                float sb2 = s_sc3[c2 + 1], hb = s_sh3[c2 + 1];
#pragma unroll
                for (int p4 = 0; p4 < 4; p4++) {
                    float2 f = unpack2(acc[p][p4]);
                    s_a[c2 * 256 + pix0 + p4]       = fmaf(sa, fmaxf(f.x, 0.f), ha);
                    s_a[(c2 + 1) * 256 + pix0 + p4] = fmaf(sb2, fmaxf(f.y, 0.f), hb);
                }
            }
        }
        __syncthreads();
    }

    // fused 2x2 maxpool -> g_x1p. active: d3 result in s_a; inactive: s_xc intact.
    const float* srcp = s_active ? s_a : s_xc;
#pragma unroll
    for (int k = 0; k < 4; k++) {
        int o = tid + k * 256;
        int c = o >> 6;
        int q = o & 63;
        int qy = q >> 3, qx = q & 7;
        const float* sp = &srcp[c * 256 + (qy * 2) * 16 + qx * 2];
        float mo = fmaxf(fmaxf(sp[0], sp[1]), fmaxf(sp[16], sp[17]));
        g_x1p[((n * 16 + c) * 256 + by * 8 + qy) * 256 + (bx * 8 + qx)] = mo;
    }
}

// ---------------------------------------------------------------------------
// Stage 2: g_x1p[16,16,256,256] -> g_x2p[16,8,128,128]
// ---------------------------------------------------------------------------
__global__ void __launch_bounds__(256) stage2_kernel(
    const float* __restrict__ cw, const float* __restrict__ cb, const float* __restrict__ bn0,
    const float* __restrict__ d1w, const float* __restrict__ d1b, const float* __restrict__ bn1,
    const float* __restrict__ d2w, const float* __restrict__ d2b, const float* __restrict__ bn2,
    const float* __restrict__ d3w, const float* __restrict__ d3b, const float* __restrict__ bn3)
{
    __shared__ float s_a[16 * 256];
    __shared__ float s_b[16 * 256];         // s_xc aliases first 8*256
    float* s_xc = s_b;
    __shared__ float2 w2d2[1152];           // [c1=16][tap=9][pair=8]
    __shared__ float2 w2d1[64];             // [c1=8][pair=8]
    __shared__ float2 w2d3[64];             // [c1=16][pair=4]
    float* w2d2f = (float*)w2d2;
    float* w2d1f = (float*)w2d1;
    float* w2d3f = (float*)w2d3;

    __shared__ float s_wsum[8];
    __shared__ float s_sc0[8],  s_sh0[8];
    __shared__ float s_sc1[16], s_sh1[16];
    __shared__ float s_sc2[16], s_sh2[16];
    __shared__ float s_sc3[8],  s_sh3[8];
    __shared__ int s_active;

    const int bid = blockIdx.x;
    const int n   = bid >> 8;
    const int by  = (bid >> 4) & 15;
    const int bx  = bid & 15;
    const int tid = threadIdx.x;
    const int py  = tid >> 4, px_ = tid & 15;
    const int gy  = by * 16 + py, gx = bx * 16 + px_;

    if (tid < 8) {
        float g = bn0[tid], b = bn0[8 + tid], m = bn0[16 + tid], v = bn0[24 + tid];
        float s = g * rsqrtf(v + EPSV); s_sc0[tid] = s; s_sh0[tid] = b - s * m;
    } else if (tid < 24) {
        int c = tid - 8;
        float g = bn1[c], b = bn1[16 + c], m = bn1[32 + c], v = bn1[48 + c];
        float s = g * rsqrtf(v + EPSV); s_sc1[c] = s; s_sh1[c] = b - s * m;
    } else if (tid < 40) {
        int c = tid - 24;
        float g = bn2[c], b = bn2[16 + c], m = bn2[32 + c], v = bn2[48 + c];
        float s = g * rsqrtf(v + EPSV); s_sc2[c] = s; s_sh2[c] = b - s * m;
    } else if (tid < 48) {
        int c = tid - 40;
        float g = bn3[c], b = bn3[8 + c], m = bn3[16 + c], v = bn3[24 + c];
        float s = g * rsqrtf(v + EPSV); s_sc3[c] = s; s_sh3[c] = b - s * m;
    }

    // activity from pooled mask (shuffle reduce)
    {
        float mv = g_mask2[(n * 256 + gy) * 256 + gx];
#pragma unroll
        for (int o = 16; o; o >>= 1) mv += __shfl_xor_sync(0xffffffffu, mv, o);
        if ((tid & 31) == 0) s_wsum[tid >> 5] = mv;
    }
    __syncthreads();
    if (tid == 0) {
        float t = 0.f;
#pragma unroll
        for (int i = 0; i < 8; i++) t += s_wsum[i];
        s_active = (t > 128.0f) ? 1 : 0;
    }

    // channel path: 1x1 conv 16->8 + bias, relu, bn
    {
        const int ibase = ((n * 16) * 256 + gy) * 256 + gx;
        float xin[16];
#pragma unroll
        for (int c = 0; c < 16; c++) xin[c] = g_x1p[ibase + c * 65536];
#pragma unroll
        for (int c2 = 0; c2 < 8; c2++) {
            float t = __ldg(&cb[c2]);
#pragma unroll
            for (int c1 = 0; c1 < 16; c1++)
                t = fmaf(xin[c1], __ldg(&cw[c2 * 16 + c1]), t);
            t = fmaxf(t, 0.0f);
            s_xc[c2 * 256 + tid] = fmaf(s_sc0[c2], t, s_sh0[c2]);
        }
    }
    __syncthreads();

    const int c2g  = tid >> 6;
    const int pg   = tid & 63;
    const int prow = pg >> 2;
    const int pcol = (pg & 3) * 4;
    const int pix0 = prow * 16 + pcol;

    if (s_active) {
        // weight prep (coalesced)
        for (int i = tid; i < 2304; i += 256) {      // d2w [16][16][9]
            int c2 = i / 144, rem = i - c2 * 144;
            int c1 = rem / 9, t = rem - c1 * 9;
            w2d2f[((c1 * 9 + t) * 8 + (c2 >> 1)) * 2 + (c2 & 1)] = d2w[i];
        }
        if (tid < 128) {                             // d1w [16][8]
            int c2 = tid >> 3, c1 = tid & 7;
            w2d1f[(c1 * 8 + (c2 >> 1)) * 2 + (c2 & 1)] = d1w[tid];
        } else if (tid < 256) {                      // d3w [8][16]
            int i = tid - 128;
            int c2 = i >> 4, c1 = i & 15;
            w2d3f[(c1 * 4 + (c2 >> 1)) * 2 + (c2 & 1)] = d3w[i];
        }
        __syncthreads();

        // ---- d1: 1x1, 8 -> 16 ----
        {
            const int pbase = c2g * 2;   // of 8 pairs
            ull acc[2][4];
#pragma unroll
            for (int p = 0; p < 2; p++) {
                int c2 = 2 * (pbase + p);
                ull bv = pack2(__ldg(&d1b[c2]), __ldg(&d1b[c2 + 1]));
                acc[p][0] = bv; acc[p][1] = bv; acc[p][2] = bv; acc[p][3] = bv;
            }
#pragma unroll
            for (int c1 = 0; c1 < 8; c1++) {
                float4 v = *(const float4*)&s_xc[c1 * 256 + pix0];
                ull vd[4] = {dup2(v.x), dup2(v.y), dup2(v.z), dup2(v.w)};
                ulonglong2 w = *(const ulonglong2*)(w2d1 + c1 * 8 + pbase);
#pragma unroll
                for (int p4 = 0; p4 < 4; p4++) {
                    fma2(acc[0][p4], w.x, vd[p4]);
                    fma2(acc[1][p4], w.y, vd[p4]);
                }
            }
#pragma unroll
            for (int p = 0; p < 2; p++) {
                int c2 = 2 * (pbase + p);
                float sa = s_sc1[c2], ha = s_sh1[c2];
                float sb2 = s_sc1[c2 + 1], hb = s_sh1[c2 + 1];
#pragma unroll
                for (int p4 = 0; p4 < 4; p4++) {
                    float2 f = unpack2(acc[p][p4]);
                    s_a[c2 * 256 + pix0 + p4]       = fmaf(sa, fmaxf(f.x, 0.f), ha);
                    s_a[(c2 + 1) * 256 + pix0 + p4] = fmaf(sb2, fmaxf(f.y, 0.f), hb);
                }
            }
        }
        __syncthreads();

        // ---- d2: 3x3, 16 -> 16 ----
        {
            const int pbase = c2g * 2;
            ull acc[2][4];
#pragma unroll
            for (int p = 0; p < 2; p++) {
                int c2 = 2 * (pbase + p);
                ull bv = pack2(__ldg(&d2b[c2]), __ldg(&d2b[c2 + 1]));
                acc[p][0] = bv; acc[p][1] = bv; acc[p][2] = bv; acc[p][3] = bv;
            }
            const float* basep = s_a + pcol;
#pragma unroll 2
            for (int c1 = 0; c1 < 16; c1++) {
                const float* cbase = basep + c1 * 256;
#pragma unroll
                for (int r = 0; r < 3; r++) {
                    int yy = prow - 1 + r;
                    float v0, v1, v2, v3, v4, v5;
                    if ((unsigned)yy < 16u) {
                        const float* rp = cbase + yy * 16;
                        float4 m = *(const float4*)rp;
                        v1 = m.x; v2 = m.y; v3 = m.z; v4 = m.w;
                        v0 = (pcol > 0)  ? rp[-1] : 0.f;
                        v5 = (pcol < 12) ? rp[4]  : 0.f;
                    } else { v0 = v1 = v2 = v3 = v4 = v5 = 0.f; }
                    ull vd[6] = {dup2(v0), dup2(v1), dup2(v2), dup2(v3), dup2(v4), dup2(v5)};
                    const float2* wrow = w2d2 + (c1 * 9 + r * 3) * 8 + pbase;
#pragma unroll
                    for (int dx = 0; dx < 3; dx++) {
                        ulonglong2 w = *(const ulonglong2*)(wrow + dx * 8);
#pragma unroll
                        for (int p4 = 0; p4 < 4; p4++) {
                            fma2(acc[0][p4], w.x, vd[dx + p4]);
                            fma2(acc[1][p4], w.y, vd[dx + p4]);
                        }
                    }
                }
            }
            __syncthreads();
#pragma unroll
            for (int p = 0; p < 2; p++) {
                int c2 = 2 * (pbase + p);
                float sa = s_sc2[c2], ha = s_sh2[c2];
                float sb2 = s_sc2[c2 + 1], hb = s_sh2[c2 + 1];
#pragma unroll
                for (int p4 = 0; p4 < 4; p4++) {
                    float2 f = unpack2(acc[p][p4]);
                    s_b[c2 * 256 + pix0 + p4]       = fmaf(sa, fmaxf(f.x, 0.f), ha);
                    s_b[(c2 + 1) * 256 + pix0 + p4] = fmaf(sb2, fmaxf(f.y, 0.f), hb);
                }
            }
        }
        __syncthreads();

        // ---- d3: 1x1, 16 -> 8 ----  (writes s_a)
        {
            const int pbase = c2g;       // of 4 pairs
            ull acc[4];
            {
                int c2 = 2 * pbase;
                ull bv = pack2(__ldg(&d3b[c2]), __ldg(&d3b[c2 + 1]));
                acc[0] = bv; acc[1] = bv; acc[2] = bv; acc[3] = bv;
            }
#pragma unroll
            for (int c1 = 0; c1 < 16; c1++) {
                float4 v = *(const float4*)&s_b[c1 * 256 + pix0];
                ull vd[4] = {dup2(v.x), dup2(v.y), dup2(v.z), dup2(v.w)};
                ull w = *(const ull*)(w2d3 + c1 * 4 + pbase);
#pragma unroll
                for (int p4 = 0; p4 < 4; p4++) fma2(acc[p4], w, vd[p4]);
            }
            {
                int c2 = 2 * pbase;
                float sa = s_sc3[c2], ha = s_sh3[c2];
                float sb2 = s_sc3[c2 + 1], hb = s_sh3[c2 + 1];
#pragma unroll
                for (int p4 = 0; p4 < 4; p4++) {
                    float2 f = unpack2(acc[p4]);
                    s_a[c2 * 256 + pix0 + p4]       = fmaf(sa, fmaxf(f.x, 0.f), ha);
                    s_a[(c2 + 1) * 256 + pix0 + p4] = fmaf(sb2, fmaxf(f.y, 0.f), hb);
                }
            }
        }
        __syncthreads();
    }

    // fused maxpool -> g_x2p
    const float* srcp = s_active ? s_a : s_xc;
#pragma unroll
    for (int k = 0; k < 2; k++) {
        int o = tid + k * 256;
        int c = o >> 6;
        int q = o & 63;
        int qy = q >> 3, qx = q & 7;
        const float* sp = &srcp[c * 256 + (qy * 2) * 16 + qx * 2];
        float mo = fmaxf(fmaxf(sp[0], sp[1]), fmaxf(sp[16], sp[17]));
        g_x2p[((n * 8 + c) * 128 + by * 8 + qy) * 128 + (bx * 8 + qx)] = mo;
    }
}

// ---------------------------------------------------------------------------
// FC (split-K) + softmax
// ---------------------------------------------------------------------------
__global__ void fc_partial_kernel(const float* __restrict__ fc_w)
{
    const int b = blockIdx.x;       // 0..127
    const int n = b >> 3, s = b & 7;
    const int tid = threadIdx.x;
    const float* f = g_x2p + n * 131072 + s * 16384;

    float part[10];
#pragma unroll
    for (int k = 0; k < 10; k++) part[k] = 0.0f;

    for (int j = tid; j < 16384; j += 256) {
        float fv = f[j];
#pragma unroll
        for (int k = 0; k < 10; k++)
            part[k] = fmaf(fv, __ldg(&fc_w[k * 131072 + s * 16384 + j]), part[k]);
    }

    __shared__ float sred[10][256];
#pragma unroll
    for (int k = 0; k < 10; k++) sred[k][tid] = part[k];
    __syncthreads();
    for (int st = 128; st > 0; st >>= 1) {
        if (tid < st) {
#pragma unroll
            for (int k = 0; k < 10; k++) sred[k][tid] += sred[k][tid + st];
        }
        __syncthreads();
    }
    if (tid < 10) g_fcpart[(n * 8 + s) * 10 + tid] = sred[tid][0];
}

__global__ void fc_final_kernel(const float* __restrict__ fc_b, float* __restrict__ out)
{
    const int t = threadIdx.x;
    __shared__ float s_l[16][10];
    if (t < 160) {
        int n = t / 10, k = t - n * 10;
        float a = fc_b[k];
#pragma unroll
        for (int s = 0; s < 8; s++) a += g_fcpart[(n * 8 + s) * 10 + k];
        s_l[n][k] = a;
    }
    __syncthreads();
    if (t < 16) {
        float mx = -1e30f;
#pragma unroll
        for (int k = 0; k < 10; k++) mx = fmaxf(mx, s_l[t][k]);
        float e[10], se = 0.f;
#pragma unroll
        for (int k = 0; k < 10; k++) { e[k] = expf(s_l[t][k] - mx); se += e[k]; }
        float inv = 1.0f / se;
#pragma unroll
        for (int k = 0; k < 10; k++) out[t * 10 + k] = e[k] * inv;
    }
}

// ---------------------------------------------------------------------------
extern "C" void kernel_launch(void* const* d_in, const int* in_sizes, int n_in,
                              void* d_out, int out_size)
{
    const float* x      = (const float*)d_in[0];
    const float* mask   = (const float*)d_in[1];
    const float* s1_cw  = (const float*)d_in[2];
    const float* s1_cb  = (const float*)d_in[3];
    const float* s1_bn0 = (const float*)d_in[4];
    const float* s1_d1w = (const float*)d_in[5];
    const float* s1_d1b = (const float*)d_in[6];
    const float* s1_bn1 = (const float*)d_in[7];
    const float* s1_d2w = (const float*)d_in[8];
    const float* s1_d2b = (const float*)d_in[9];
    const float* s1_bn2 = (const float*)d_in[10];
    const float* s1_d3w = (const float*)d_in[11];
    const float* s1_d3b = (const float*)d_in[12];
    const float* s1_bn3 = (const float*)d_in[13];
    const float* s2_cw  = (const float*)d_in[14];
    const float* s2_cb  = (const float*)d_in[15];
    const float* s2_bn0 = (const float*)d_in[16];
    const float* s2_d1w = (const float*)d_in[17];
    const float* s2_d1b = (const float*)d_in[18];
    const float* s2_bn1 = (const float*)d_in[19];
    const float* s2_d2w = (const float*)d_in[20];
    const float* s2_d2b = (const float*)d_in[21];
    const float* s2_bn2 = (const float*)d_in[22];
    const float* s2_d3w = (const float*)d_in[23];
    const float* s2_d3b = (const float*)d_in[24];
    const float* s2_bn3 = (const float*)d_in[25];
    const float* fc_w   = (const float*)d_in[26];
    const float* fc_b   = (const float*)d_in[27];

    const int smem1 = 26624 * sizeof(float);   // 104 KB dynamic
    cudaFuncSetAttribute(stage1_kernel, cudaFuncAttributeMaxDynamicSharedMemorySize, smem1);

    stage1_kernel<<<16 * 32 * 32, 256, smem1>>>(
        x, mask, s1_cw, s1_cb, s1_bn0, s1_d1w, s1_d1b, s1_bn1,
        s1_d2w, s1_d2b, s1_bn2, s1_d3w, s1_d3b, s1_bn3);

    stage2_kernel<<<16 * 16 * 16, 256>>>(
        s2_cw, s2_cb, s2_bn0, s2_d1w, s2_d1b, s2_bn1,
        s2_d2w, s2_d2b, s2_bn2, s2_d3w, s2_d3b, s2_bn3);

    fc_partial_kernel<<<128, 256>>>(fc_w);
    fc_final_kernel<<<1, 256>>>(fc_b, (float*)d_out);
}